// round 12
// baseline (speedup 1.0000x reference)
#include <cuda_runtime.h>
#include <cstddef>
#include <cstdint>

// Problem constants (fixed shapes from setup_inputs)
#define C_    32
#define H_    192
#define W_    256
#define S_    9
#define G_    8
#define HW_   (H_*W_)            // 49152
#define HWS_  ((size_t)HW_*S_)   // 442368
#define CHWS_ ((size_t)C_*HWS_)

#define TPB_A 64                 // att kernel: pixels per CTA
#define TPB_B 128                // stream kernel: pixels per CTA
#define NSPL  4                  // source-image split across blockIdx.y
#define NPER  (8/NSPL)           // 2 images per CTA
#define NT    (1+NPER)           // tiles per stage: ref + NPER src
#define T4    (TPB_B*S_/4)       // float4 per tile = 288
#define RING  3                  // pipeline stages

__device__ float g_att[S_ * HW_];   // att scratch, SoA: [s][p] (coalesced)

// ---- cp.async helpers ----
__device__ __forceinline__ void cp16(uint32_t dst, const void* src) {
    asm volatile("cp.async.cg.shared.global [%0], [%1], 16;\n" :: "r"(dst), "l"(src));
}
__device__ __forceinline__ void cp_commit() {
    asm volatile("cp.async.commit_group;\n" ::: "memory");
}
template<int N> __device__ __forceinline__ void cp_wait() {
    asm volatile("cp.async.wait_group %0;\n" :: "n"(N) : "memory");
}

// ---------------- kernel A: attention weights (prep folded; scalar, barrier-free body) ----------------
__global__ void __launch_bounds__(TPB_A, 10)
att_kernel(const float* __restrict__ f, const float* __restrict__ Wp,
           const float* __restrict__ bp) {
    __shared__ float Wsm[C_*C_];       // Wp row-major [d][c]
    const int tid = threadIdx.x;
    const int p   = blockIdx.x * TPB_A + tid;
    const float* __restrict__ refp = f + (size_t)p * S_;

    {   // stage Wp (256 float4 / 64 threads)
        float4* W4 = (float4*)Wsm;
        const float4* Wg = (const float4*)Wp;
        #pragma unroll
        for (int k = 0; k < 4; k++) W4[tid + TPB_A*k] = Wg[tid + TPB_A*k];
    }
    __syncthreads();

    // r_mid (s=4)
    float rm[C_];
    #pragma unroll
    for (int c = 0; c < C_; c++) rm[c] = __ldg(refp + (size_t)c * HWS_ + 4);

    // u = Wp rm + bp ; tv = Wp^T u   (uniform SMEM reads -> broadcast)
    float u[C_];
    #pragma unroll
    for (int d = 0; d < C_; d++) {
        float a = __ldg(bp + d);
        #pragma unroll
        for (int c = 0; c < C_; c++) a += Wsm[d*C_ + c] * rm[c];
        u[d] = a;
    }
    float tv[C_];
    #pragma unroll
    for (int c = 0; c < C_; c++) {
        float a = 0.f;
        #pragma unroll
        for (int d = 0; d < C_; d++) a += u[d] * Wsm[d*C_ + c];
        tv[c] = a;
    }

    // logits (scalar loads; aggregate-coalesced across warp)
    float l[S_];
    #pragma unroll
    for (int s = 0; s < S_; s++) l[s] = 0.f;
    #pragma unroll 4
    for (int c = 0; c < C_; c++) {
        const float* rp = refp + (size_t)c * HWS_;
        const float t = tv[c];
        #pragma unroll
        for (int s = 0; s < S_; s++) l[s] += t * __ldg(rp + s);
    }

    // softmax over s (shift-invariant terms dropped)
    const float inv_sqrtC = 0.17677669529663687f;   // 1/sqrt(32)
    float mx = l[0];
    #pragma unroll
    for (int s = 1; s < S_; s++) mx = fmaxf(mx, l[s]);
    float e[S_], sum = 0.f;
    #pragma unroll
    for (int s = 0; s < S_; s++) { e[s] = __expf((l[s] - mx) * inv_sqrtC); sum += e[s]; }
    const float isum = __frcp_rn(sum);
    #pragma unroll
    for (int s = 0; s < S_; s++) g_att[s * HW_ + p] = e[s] * isum;
}

// ---------------- kernel B: cp.async-pipelined source streaming ----------------
// c-steps 0..31; 3-slot SMEM ring; one __syncthreads per step; issue AFTER the
// barrier so slot (c+2)%3 (consumed at step c-1) is never overwritten early.
__global__ void __launch_bounds__(TPB_B, 5)
stream_kernel(const float* __restrict__ f, float* __restrict__ out) {
    __shared__ float4 ring[RING][NT*T4];   // 3 * 3 * 288 float4 = 41472 B

    const int tid = threadIdx.x;
    const int p0  = blockIdx.x * TPB_B;
    const int p   = p0 + tid;
    const int n0  = blockIdx.y * NPER;

    float att[S_];
    #pragma unroll
    for (int s = 0; s < S_; s++) att[s] = __ldg(&g_att[s * HW_ + p]);

    const uint32_t ring_s = (uint32_t)__cvta_generic_to_shared(&ring[0][0]);

    // stage channel c into slot: NT tiles of 288 float4 each
    auto issue = [&](int c, int slot) {
        const uint32_t base = ring_s + (uint32_t)slot * (NT*T4*16);
        #pragma unroll
        for (int t = 0; t < NT; t++) {
            const int img = (t == 0) ? 0 : (n0 + t);      // 0=ref, else source n0+t-1 -> f image index n0+t
            const char* g = (const char*)(f + (size_t)img*CHWS_ + (size_t)c*HWS_ + (size_t)p0*S_);
            const uint32_t d = base + (uint32_t)t * (T4*16);
            cp16(d + (uint32_t)tid*16,            g + (size_t)tid*16);
            cp16(d + (uint32_t)(tid+TPB_B)*16,    g + (size_t)(tid+TPB_B)*16);
            if (tid < T4 - 2*TPB_B)               // 32 remaining
                cp16(d + (uint32_t)(tid+2*TPB_B)*16, g + (size_t)(tid+2*TPB_B)*16);
        }
        cp_commit();
    };

    // prologue: prefetch c=0,1
    issue(0, 0);
    issue(1, 1);

    float acc[NPER];
    #pragma unroll 1
    for (int c = 0; c < C_; c++) {
        const int cc = c & 3;
        const int g  = c >> 2;
        if (cc == 0) {
            #pragma unroll
            for (int n = 0; n < NPER; n++) acc[n] = 0.f;
        }

        cp_wait<1>();          // slot c%3 ready (group c complete)
        __syncthreads();       // staged data visible to all; prior slot fully consumed

        if (c + 2 < C_) issue(c + 2, (c + 2) % RING);
        else            cp_commit();   // empty group keeps wait_group<1> semantics aligned

        const float* sf = (const float*)&ring[c % RING][0];
        float w[S_];
        #pragma unroll
        for (int s = 0; s < S_; s++) w[s] = sf[tid*S_ + s] * att[s];
        #pragma unroll
        for (int n = 0; n < NPER; n++) {
            const float* sn = sf + (1+n)*(TPB_B*S_) + tid*S_;
            float a = 0.f;
            #pragma unroll
            for (int s = 0; s < S_; s++) a += w[s] * sn[s];
            acc[n] += a;
        }

        if (cc == 3) {
            #pragma unroll
            for (int n = 0; n < NPER; n++)
                out[(size_t)((n0 + n)*G_ + g)*HW_ + p] = acc[n];
        }
    }
}

extern "C" void kernel_launch(void* const* d_in, const int* in_sizes, int n_in,
                              void* d_out, int out_size) {
    // Identify inputs by element count: f = 127401984, Wp = 1024, bp = 32
    const float* f  = nullptr;
    const float* Wp = nullptr;
    const float* bp = nullptr;
    for (int i = 0; i < n_in; i++) {
        if      (in_sizes[i] == 127401984) f  = (const float*)d_in[i];
        else if (in_sizes[i] == 1024)      Wp = (const float*)d_in[i];
        else if (in_sizes[i] == 32)        bp = (const float*)d_in[i];
    }
    if (!f || !Wp || !bp) {  // fallback positional
        f  = (const float*)d_in[0];
        Wp = (const float*)d_in[1];
        bp = (const float*)d_in[2];
    }
    float* out = (float*)d_out;

    att_kernel<<<HW_/TPB_A, TPB_A>>>(f, Wp, bp);
    dim3 gridB(HW_/TPB_B, NSPL);
    stream_kernel<<<gridB, TPB_B>>>(f, out);
}

// round 13
// speedup vs baseline: 1.3634x; 1.3634x over previous
#include <cuda_runtime.h>
#include <cstddef>
#include <cstdint>

// Problem constants (fixed shapes from setup_inputs)
#define C_    32
#define H_    192
#define W_    256
#define S_    9
#define G_    8
#define HW_   (H_*W_)            // 49152
#define HWS_  ((size_t)HW_*S_)   // 442368
#define CHWS_ ((size_t)C_*HWS_)

#define TPB_A 64                 // att kernel: pixels per CTA
#define TPB_B 128                // stream kernel: pixels per CTA
#define NSPL  8                  // source-image split across blockIdx.y
#define NPER  (8/NSPL)           // 1 image per CTA
#define NT    (1+NPER)           // tiles per stage: ref + 1 src
#define T4    (TPB_B*S_/4)       // float4 per tile = 288
#define RING  3                  // pipeline stages

__device__ float g_att[S_ * HW_];   // att scratch, SoA: [s][p] (coalesced)

// ---- cp.async helpers ----
__device__ __forceinline__ void cp16(uint32_t dst, const void* src) {
    asm volatile("cp.async.cg.shared.global [%0], [%1], 16;\n" :: "r"(dst), "l"(src));
}
__device__ __forceinline__ void cp_commit() {
    asm volatile("cp.async.commit_group;\n" ::: "memory");
}
template<int N> __device__ __forceinline__ void cp_wait() {
    asm volatile("cp.async.wait_group %0;\n" :: "n"(N) : "memory");
}

// ---------------- kernel A: attention weights (prep folded, spill-free) ----------------
// u = Wp rm + bp  (rm dies), then tvc folded per channel: peak live ~70 regs.
__global__ void __launch_bounds__(TPB_A, 8)
att_kernel(const float* __restrict__ f, const float* __restrict__ Wp,
           const float* __restrict__ bp) {
    __shared__ float Wsm[C_*C_];       // Wp row-major [d][c]
    const int tid = threadIdx.x;
    const int p   = blockIdx.x * TPB_A + tid;
    const float* __restrict__ refp = f + (size_t)p * S_;

    {   // stage Wp (256 float4 / 64 threads)
        float4* W4 = (float4*)Wsm;
        const float4* Wg = (const float4*)Wp;
        #pragma unroll
        for (int k = 0; k < 4; k++) W4[tid + TPB_A*k] = Wg[tid + TPB_A*k];
    }
    __syncthreads();

    // u = Wp rm + bp   (rm scoped so it dies before logits)
    float u[C_];
    {
        float rm[C_];
        #pragma unroll
        for (int c = 0; c < C_; c++) rm[c] = __ldg(refp + (size_t)c * HWS_ + 4);
        #pragma unroll
        for (int d = 0; d < C_; d++) {
            float a0 = 0.f, a1 = 0.f, a2 = 0.f, a3 = 0.f;
            const float* row = Wsm + d*C_;
            #pragma unroll
            for (int c = 0; c < C_; c += 4) {
                a0 += row[c]   * rm[c];
                a1 += row[c+1] * rm[c+1];
                a2 += row[c+2] * rm[c+2];
                a3 += row[c+3] * rm[c+3];
            }
            u[d] = ((a0 + a1) + (a2 + a3)) + __ldg(bp + d);
        }
    }

    // logits: l[s] += tvc * r[c][s],  tvc = sum_d u[d]*Wp[d][c] (folded scalar)
    float l[S_];
    #pragma unroll
    for (int s = 0; s < S_; s++) l[s] = 0.f;
    #pragma unroll 4
    for (int c = 0; c < C_; c++) {
        float t0 = 0.f, t1 = 0.f;
        #pragma unroll
        for (int d = 0; d < C_; d += 2) {
            t0 += u[d]   * Wsm[d*C_ + c];
            t1 += u[d+1] * Wsm[(d+1)*C_ + c];
        }
        const float tvc = t0 + t1;
        const float* rp = refp + (size_t)c * HWS_;
        #pragma unroll
        for (int s = 0; s < S_; s++) l[s] += tvc * __ldg(rp + s);
    }

    // softmax over s (shift-invariant terms dropped)
    const float inv_sqrtC = 0.17677669529663687f;   // 1/sqrt(32)
    float mx = l[0];
    #pragma unroll
    for (int s = 1; s < S_; s++) mx = fmaxf(mx, l[s]);
    float e[S_], sum = 0.f;
    #pragma unroll
    for (int s = 0; s < S_; s++) { e[s] = __expf((l[s] - mx) * inv_sqrtC); sum += e[s]; }
    const float isum = __frcp_rn(sum);
    #pragma unroll
    for (int s = 0; s < S_; s++) g_att[s * HW_ + p] = e[s] * isum;
}

// ---------------- kernel B: cp.async-pipelined source streaming (NSPL=8) ----------------
// Stage = ref tile + 1 src tile (9.2 KB); ring of 3 => 27.6 KB, 8 CTAs/SM.
__global__ void __launch_bounds__(TPB_B, 8)
stream_kernel(const float* __restrict__ f, float* __restrict__ out) {
    __shared__ float4 ring[RING][NT*T4];   // 3 * 2 * 288 float4 = 27648 B

    const int tid = threadIdx.x;
    const int p0  = blockIdx.x * TPB_B;
    const int p   = p0 + tid;
    const int n0  = blockIdx.y;            // this CTA's single source image (0..7)

    float att[S_];
    #pragma unroll
    for (int s = 0; s < S_; s++) att[s] = __ldg(&g_att[s * HW_ + p]);

    const uint32_t ring_s = (uint32_t)__cvta_generic_to_shared(&ring[0][0]);

    // stage channel c into slot: NT tiles of 288 float4 each
    auto issue = [&](int c, int slot) {
        const uint32_t base = ring_s + (uint32_t)slot * (NT*T4*16);
        #pragma unroll
        for (int t = 0; t < NT; t++) {
            const int img = (t == 0) ? 0 : (n0 + 1);   // ref, then source image n0
            const char* g = (const char*)(f + (size_t)img*CHWS_ + (size_t)c*HWS_ + (size_t)p0*S_);
            const uint32_t d = base + (uint32_t)t * (T4*16);
            cp16(d + (uint32_t)tid*16,            g + (size_t)tid*16);
            cp16(d + (uint32_t)(tid+TPB_B)*16,    g + (size_t)(tid+TPB_B)*16);
            if (tid < T4 - 2*TPB_B)               // 32 remaining
                cp16(d + (uint32_t)(tid+2*TPB_B)*16, g + (size_t)(tid+2*TPB_B)*16);
        }
        cp_commit();
    };

    // prologue: prefetch c=0,1
    issue(0, 0);
    issue(1, 1);

    float acc = 0.f;
    #pragma unroll 1
    for (int c = 0; c < C_; c++) {
        cp_wait<1>();          // group c complete (slot c%3 ready)
        __syncthreads();       // visible to all; slot (c+2)%3 fully consumed at step c-1

        if (c + 2 < C_) issue(c + 2, (c + 2) % RING);
        else            cp_commit();   // keep wait_group<1> group-count semantics aligned

        const float* sf = (const float*)&ring[c % RING][0];
        const float* rr = sf + tid*S_;                // ref row (9-float stride: bank-clean)
        const float* sn = sf + (TPB_B*S_) + tid*S_;   // src row
        float a = 0.f;
        #pragma unroll
        for (int s = 0; s < S_; s++) a += (rr[s] * att[s]) * sn[s];
        acc += a;

        if ((c & 3) == 3) {
            out[(size_t)(n0*G_ + (c >> 2))*HW_ + p] = acc;
            acc = 0.f;
        }
    }
}

extern "C" void kernel_launch(void* const* d_in, const int* in_sizes, int n_in,
                              void* d_out, int out_size) {
    // Identify inputs by element count: f = 127401984, Wp = 1024, bp = 32
    const float* f  = nullptr;
    const float* Wp = nullptr;
    const float* bp = nullptr;
    for (int i = 0; i < n_in; i++) {
        if      (in_sizes[i] == 127401984) f  = (const float*)d_in[i];
        else if (in_sizes[i] == 1024)      Wp = (const float*)d_in[i];
        else if (in_sizes[i] == 32)        bp = (const float*)d_in[i];
    }
    if (!f || !Wp || !bp) {  // fallback positional
        f  = (const float*)d_in[0];
        Wp = (const float*)d_in[1];
        bp = (const float*)d_in[2];
    }
    float* out = (float*)d_out;

    att_kernel<<<HW_/TPB_A, TPB_A>>>(f, Wp, bp);
    dim3 gridB(HW_/TPB_B, NSPL);
    stream_kernel<<<gridB, TPB_B>>>(f, out);
}

// round 14
// speedup vs baseline: 1.5704x; 1.1518x over previous
#include <cuda_runtime.h>
#include <cstddef>
#include <cstdint>

// Problem constants (fixed shapes from setup_inputs)
#define C_    32
#define H_    192
#define W_    256
#define S_    9
#define G_    8
#define HW_   (H_*W_)            // 49152
#define HWS_  ((size_t)HW_*S_)   // 442368
#define CHWS_ ((size_t)C_*HWS_)

#define TPB_A 128                // att kernel: pixels per CTA
#define TPB_B 128                // stream kernel: pixels per CTA
#define NSPL  8                  // source-image split (grid dim, launch-adjacent!)
#define NPER  (8/NSPL)           // 1 image per CTA
#define NT    (1+NPER)           // tiles per stage in stream kernel: ref + 1 src
#define T4A   (TPB_A*S_/4)       // float4 per att tile = 288
#define T4    (TPB_B*S_/4)       // float4 per stream tile = 288
#define RING  3                  // pipeline stages

__device__ float g_att[S_ * HW_];   // att scratch, SoA: [s][p] (coalesced)

// ---- cp.async helpers ----
__device__ __forceinline__ void cp16(uint32_t dst, const void* src) {
    asm volatile("cp.async.cg.shared.global [%0], [%1], 16;\n" :: "r"(dst), "l"(src));
}
__device__ __forceinline__ void cp_commit() {
    asm volatile("cp.async.commit_group;\n" ::: "memory");
}
template<int N> __device__ __forceinline__ void cp_wait() {
    asm volatile("cp.async.wait_group %0;\n" :: "n"(N) : "memory");
}

// ---------------- kernel A: attention weights, cp.async-pipelined ----------------
// Ref tiles staged through a 3-slot ring (float4, perfectly coalesced); the
// u = Wp rm + bp matvec overlaps the first prefetches. One barrier per channel.
__global__ void __launch_bounds__(TPB_A, 8)
att_kernel(const float* __restrict__ f, const float* __restrict__ Wp,
           const float* __restrict__ bp) {
    __shared__ float  Wsm[C_*C_];          // Wp row-major [d][c], 4 KB
    __shared__ float4 ring[RING][T4A];     // 3 * 288 float4 = 13.8 KB

    const int tid = threadIdx.x;
    const int p0  = blockIdx.x * TPB_A;
    const int p   = p0 + tid;

    {   // stage Wp (256 float4 / 128 threads)
        float4* W4 = (float4*)Wsm;
        const float4* Wg = (const float4*)Wp;
        W4[tid] = Wg[tid];
        if (tid < 128) W4[tid + 128] = Wg[tid + 128];
    }

    const uint32_t ring_s = (uint32_t)__cvta_generic_to_shared(&ring[0][0]);
    auto issue = [&](int c, int slot) {
        const uint32_t base = ring_s + (uint32_t)slot * (T4A*16);
        const char* g = (const char*)(f + (size_t)c*HWS_ + (size_t)p0*S_);
        cp16(base + (uint32_t)tid*16,           g + (size_t)tid*16);
        cp16(base + (uint32_t)(tid+TPB_A)*16,   g + (size_t)(tid+TPB_A)*16);
        if (tid < T4A - 2*TPB_A)                // 32 remaining
            cp16(base + (uint32_t)(tid+2*TPB_A)*16, g + (size_t)(tid+2*TPB_A)*16);
        cp_commit();
    };

    issue(0, 0);
    issue(1, 1);
    __syncthreads();           // Wsm visible (also orders nothing for cp.async ring yet)

    // u = Wp rm + bp, overlapped with the in-flight prefetches (rm scoped: dies here)
    float u[C_];
    {
        float rm[C_];
        #pragma unroll
        for (int c = 0; c < C_; c++)
            rm[c] = __ldg(f + (size_t)c*HWS_ + (size_t)p*S_ + 4);
        #pragma unroll
        for (int d = 0; d < C_; d++) {
            float a0 = 0.f, a1 = 0.f;
            const float* row = Wsm + d*C_;
            #pragma unroll
            for (int c = 0; c < C_; c += 2) {
                a0 += row[c]   * rm[c];
                a1 += row[c+1] * rm[c+1];
            }
            u[d] = (a0 + a1) + __ldg(bp + d);
        }
    }

    float l[S_];
    #pragma unroll
    for (int s = 0; s < S_; s++) l[s] = 0.f;

    #pragma unroll 1
    for (int c = 0; c < C_; c++) {
        cp_wait<1>();
        __syncthreads();       // slot c%3 visible; slot (c+2)%3 fully consumed
        if (c + 2 < C_) issue(c + 2, (c + 2) % RING);
        else            cp_commit();   // keep group-count semantics aligned

        // tvc = sum_d u[d]*Wp[d][c]  (uniform SMEM reads -> broadcast)
        float t0 = 0.f, t1 = 0.f;
        #pragma unroll
        for (int d = 0; d < C_; d += 2) {
            t0 += u[d]   * Wsm[d*C_ + c];
            t1 += u[d+1] * Wsm[(d+1)*C_ + c];
        }
        const float tvc = t0 + t1;

        const float* r = (const float*)&ring[c % RING][0] + tid*S_;  // bank-clean
        #pragma unroll
        for (int s = 0; s < S_; s++) l[s] += tvc * r[s];
    }

    // softmax over s (shift-invariant terms dropped)
    const float inv_sqrtC = 0.17677669529663687f;   // 1/sqrt(32)
    float mx = l[0];
    #pragma unroll
    for (int s = 1; s < S_; s++) mx = fmaxf(mx, l[s]);
    float e[S_], sum = 0.f;
    #pragma unroll
    for (int s = 0; s < S_; s++) { e[s] = __expf((l[s] - mx) * inv_sqrtC); sum += e[s]; }
    const float isum = __frcp_rn(sum);
    #pragma unroll
    for (int s = 0; s < S_; s++) g_att[s * HW_ + p] = e[s] * isum;
}

// ---------------- kernel B: cp.async-pipelined source streaming ----------------
// grid = (NSPL, HW/TPB): the 8 n-copies of a pixel block are launch-ADJACENT,
// so ref tiles are DRAM-fetched once and L2-hit by the other 7 copies.
__global__ void __launch_bounds__(TPB_B, 8)
stream_kernel(const float* __restrict__ f, float* __restrict__ out) {
    __shared__ float4 ring[RING][NT*T4];   // 3 * 2 * 288 float4 = 27648 B

    const int tid = threadIdx.x;
    const int n0  = blockIdx.x;            // source image (0..7)
    const int p0  = blockIdx.y * TPB_B;
    const int p   = p0 + tid;

    float att[S_];
    #pragma unroll
    for (int s = 0; s < S_; s++) att[s] = __ldg(&g_att[s * HW_ + p]);

    const uint32_t ring_s = (uint32_t)__cvta_generic_to_shared(&ring[0][0]);

    auto issue = [&](int c, int slot) {
        const uint32_t base = ring_s + (uint32_t)slot * (NT*T4*16);
        #pragma unroll
        for (int t = 0; t < NT; t++) {
            const int img = (t == 0) ? 0 : (n0 + 1);   // ref, then source image n0
            const char* g = (const char*)(f + (size_t)img*CHWS_ + (size_t)c*HWS_ + (size_t)p0*S_);
            const uint32_t d = base + (uint32_t)t * (T4*16);
            cp16(d + (uint32_t)tid*16,            g + (size_t)tid*16);
            cp16(d + (uint32_t)(tid+TPB_B)*16,    g + (size_t)(tid+TPB_B)*16);
            if (tid < T4 - 2*TPB_B)               // 32 remaining
                cp16(d + (uint32_t)(tid+2*TPB_B)*16, g + (size_t)(tid+2*TPB_B)*16);
        }
        cp_commit();
    };

    issue(0, 0);
    issue(1, 1);

    float acc = 0.f;
    #pragma unroll 1
    for (int c = 0; c < C_; c++) {
        cp_wait<1>();          // group c complete (slot c%3 ready)
        __syncthreads();       // visible to all; slot (c+2)%3 fully consumed

        if (c + 2 < C_) issue(c + 2, (c + 2) % RING);
        else            cp_commit();   // keep wait_group<1> semantics aligned

        const float* sf = (const float*)&ring[c % RING][0];
        const float* rr = sf + tid*S_;                // ref row (bank-clean)
        const float* sn = sf + (TPB_B*S_) + tid*S_;   // src row
        float a = 0.f;
        #pragma unroll
        for (int s = 0; s < S_; s++) a += (rr[s] * att[s]) * sn[s];
        acc += a;

        if ((c & 3) == 3) {
            out[(size_t)(n0*G_ + (c >> 2))*HW_ + p] = acc;
            acc = 0.f;
        }
    }
}

extern "C" void kernel_launch(void* const* d_in, const int* in_sizes, int n_in,
                              void* d_out, int out_size) {
    // Identify inputs by element count: f = 127401984, Wp = 1024, bp = 32
    const float* f  = nullptr;
    const float* Wp = nullptr;
    const float* bp = nullptr;
    for (int i = 0; i < n_in; i++) {
        if      (in_sizes[i] == 127401984) f  = (const float*)d_in[i];
        else if (in_sizes[i] == 1024)      Wp = (const float*)d_in[i];
        else if (in_sizes[i] == 32)        bp = (const float*)d_in[i];
    }
    if (!f || !Wp || !bp) {  // fallback positional
        f  = (const float*)d_in[0];
        Wp = (const float*)d_in[1];
        bp = (const float*)d_in[2];
    }
    float* out = (float*)d_out;

    att_kernel<<<HW_/TPB_A, TPB_A>>>(f, Wp, bp);
    dim3 gridB(NSPL, HW_/TPB_B);
    stream_kernel<<<gridB, TPB_B>>>(f, out);
}